// round 17
// baseline (speedup 1.0000x reference)
#include <cuda_runtime.h>
#include <cuda_bf16.h>
#include <math.h>
#include <stdint.h>

// ---------------- problem constants ----------------
#define NTOK (2*8*128*128)          // 262144 tokens
#define NWIN (NTOK/128)             // 2048 windows
// SCALE * log2(e) folded into q at QKV epilogue:
#define QSCALE 0.36067376022224085f

// ---------------- scratch ----------------
__device__ __nv_bfloat16 g_wb [110592];              // bf16 weights
__device__ float         g_y  [(size_t)NTOK * 96];   // first residual (natural, fp32)

#define WB_QKV  0
#define WB_PROJ 27648
#define WB_FC1  36864
#define WB_FC2  73728

static __device__ __forceinline__ uint32_t s2u(const void* p) {
    return (uint32_t)__cvta_generic_to_shared(p);
}

#define LDSM_X4(r0,r1,r2,r3,addr) \
    asm volatile("ldmatrix.sync.aligned.m8n8.x4.shared.b16 {%0,%1,%2,%3}, [%4];" \
        : "=r"(r0),"=r"(r1),"=r"(r2),"=r"(r3) : "r"(addr))

#define LDSM_X4_T(r0,r1,r2,r3,addr) \
    asm volatile("ldmatrix.sync.aligned.m8n8.x4.trans.shared.b16 {%0,%1,%2,%3}, [%4];" \
        : "=r"(r0),"=r"(r1),"=r"(r2),"=r"(r3) : "r"(addr))

#define MMA_BF16(c,a0,a1,a2,a3,b0,b1) \
    asm volatile("mma.sync.aligned.m16n8k16.row.col.f32.bf16.bf16.f32 " \
        "{%0,%1,%2,%3},{%4,%5,%6,%7},{%8,%9},{%0,%1,%2,%3};" \
        : "+f"(c[0]),"+f"(c[1]),"+f"(c[2]),"+f"(c[3]) \
        : "r"(a0),"r"(a1),"r"(a2),"r"(a3),"r"(b0),"r"(b1))

#define CP_ASYNC16(dst,src) \
    asm volatile("cp.async.cg.shared.global [%0], [%1], 16;" :: "r"(dst), "l"(src))
#define CP_COMMIT() asm volatile("cp.async.commit_group;")
#define CP_WAIT0()  asm volatile("cp.async.wait_group 0;")

static __device__ __forceinline__ float ex2f(float x) {
    float r;
    asm("ex2.approx.f32 %0, %1;" : "=f"(r) : "f"(x));
    return r;
}

static __device__ __forceinline__ float gelu_t(float v) {
    float u = 0.7978845608028654f * v * fmaf(0.044715f, v * v, 1.0f);
    float t;
    asm("tanh.approx.f32 %0, %1;" : "=f"(t) : "f"(u));
    return 0.5f * v * (1.0f + t);
}

// label bits of token n: {t: bit6, h: bit5, w: bit2}
static __device__ __forceinline__ int bits3(int n) {
    return ((n >> 6) & 1) | (((n >> 5) & 1) << 1) | (((n >> 2) & 1) << 2);
}

// ---------------- weight conversion fp32 -> bf16 ----------------
__global__ void convert_w(const float* __restrict__ wq, const float* __restrict__ wp,
                          const float* __restrict__ w1, const float* __restrict__ w2,
                          __nv_bfloat16* __restrict__ out)
{
    int i = blockIdx.x * 256 + threadIdx.x;
    if (i < 27648)       out[i] = __float2bfloat16(wq[i]);
    else if (i < 36864)  out[i] = __float2bfloat16(wp[i - 27648]);
    else if (i < 73728)  out[i] = __float2bfloat16(w1[i - 36864]);
    else if (i < 110592) out[i] = __float2bfloat16(w2[i - 73728]);
}

// ================= MONO kernel, 512 threads, 2 CTAs/SM =================
// smem (bf16 elems):
//   sQKV [0, 37888)      128x296: q-slots cols 0..95, kv-slots cols 96..287
//   pWa  [37888, 47872)  weight buffer (96x104)  -- k, then q, then Wproj
//   pLN2 [43264, 56576)  LN2 tile 128x104 (phase >= 4 only; pWa dead by then)
// v-chunk weights stage temporarily in the v-slots (cols 192..287) of sQKV.
// MLP: bufW1 in cols 96..191 (96 rows), bufW2 in cols 192..287 (96 rows),
//      hidden chunk in q-slots cols 0..95.
#define STRQ 296
#define OFF_WA  37888
#define OFF_LN2 43264
#define SMEM_MONO 113664

__global__ __launch_bounds__(512, 2) void mono_kernel(
    const float* __restrict__ x,
    const float* __restrict__ g1, const float* __restrict__ b1,
    const __nv_bfloat16* __restrict__ wqkv, const float* __restrict__ b_qkv,
    const __nv_bfloat16* __restrict__ wproj, const float* __restrict__ b_proj,
    const float* __restrict__ g2, const float* __restrict__ b2,
    const __nv_bfloat16* __restrict__ w1, const float* __restrict__ bias1,
    const __nv_bfloat16* __restrict__ w2, const float* __restrict__ bias2,
    float* __restrict__ yscr,
    float* __restrict__ out)
{
    extern __shared__ __align__(16) char smem_raw[];
    __nv_bfloat16* sQKV = (__nv_bfloat16*)smem_raw;
    __nv_bfloat16* pWa  = sQKV + OFF_WA;
    __nv_bfloat16* pLN2 = sQKV + OFF_LN2;
    float* yf = (float*)smem_raw;       // y staging: yf[row*148 + 48 + col]

    const int tid  = threadIdx.x;
    const int lane = tid & 31;
    const int warp = tid >> 5;        // 16 warps
    const int wm = warp & 7, wn = warp >> 3;   // 8m x 2n

    const int win = blockIdx.x;
    const int wr = win & 1023;
    const int tb = wr >> 8, hb = (wr >> 4) & 15, wb = wr & 15;
    const int bi = win >> 10;
    const int amask = ((tb == 3) ? 1 : 0) | ((hb == 15) ? 2 : 0) | ((wb == 15) ? 4 : 0);

    // ---- phase 0: prefetch k-chunk weights -> pWa + LN1 (shift gather) ----
    for (int gi = tid; gi < 1152; gi += 512) {
        int row = gi / 12, q = gi - row * 12;
        CP_ASYNC16(s2u(pWa + row * 104 + q * 8),
                   (const void*)(wqkv + (size_t)(96 + row) * 96 + q * 8));
    }
    CP_COMMIT();

    for (int tok = warp; tok < 128; tok += 16) {
        int dt = tok >> 6, dh = (tok >> 3) & 7, dw = tok & 7;
        int t = tb * 2 + dt, h = hb * 8 + dh, w = wb * 8 + dw;
        int ti = (t + 1) & 7, hi = (h + 4) & 127, wi = (w + 4) & 127;
        size_t src = ((size_t)((bi * 8 + ti) * 128 + hi)) * 128 + wi;
        const float* row = x + src * 96;
        float v0 = row[lane], v1 = row[lane + 32], v2 = row[lane + 64];
        float s  = v0 + v1 + v2;
        float s2 = v0 * v0 + v1 * v1 + v2 * v2;
        #pragma unroll
        for (int o = 16; o; o >>= 1) {
            s  += __shfl_xor_sync(0xffffffffu, s,  o);
            s2 += __shfl_xor_sync(0xffffffffu, s2, o);
        }
        float mean = s * (1.0f / 96.0f);
        float var  = s2 * (1.0f / 96.0f) - mean * mean;
        float rstd = rsqrtf(var + 1e-5f);
        __nv_bfloat16* orow = sQKV + tok * STRQ;
        orow[lane]      = __float2bfloat16((v0 - mean) * rstd * g1[lane]      + b1[lane]);
        orow[lane + 32] = __float2bfloat16((v1 - mean) * rstd * g1[lane + 32] + b1[lane + 32]);
        orow[lane + 64] = __float2bfloat16((v2 - mean) * rstd * g1[lane + 64] + b1[lane + 64]);
    }

    // ---- phase 1: QKV GEMM (k, v, q); A-fragments cached in registers ----
    const uint32_t aq = s2u(sQKV + (wm * 16 + (lane & 15)) * STRQ + (lane >> 4) * 8);
    const uint32_t bwA = s2u(pWa + (wn * 48 + ((lane >> 4) << 3) + (lane & 7)) * 104
                                 + ((lane >> 3) & 1) * 8);
    // v-chunk weights staged in v-slots: row stride STRQ, base col 192
    const uint32_t bwV = s2u(sQKV + (wn * 48 + ((lane >> 4) << 3) + (lane & 7)) * STRQ
                                  + 192 + ((lane >> 3) & 1) * 8);

    uint32_t afr[6][4];   // LN1 A-fragments, reused for all 3 chunks

    // -- chunk k (weights in pWa) --
    {
        CP_WAIT0();
        __syncthreads();   // k weights + LN1 visible
        #pragma unroll
        for (int ks = 0; ks < 6; ks++)
            LDSM_X4(afr[ks][0], afr[ks][1], afr[ks][2], afr[ks][3], aq + ks * 32);
        // prefetch v weights into the (empty) v-slots
        for (int gi = tid; gi < 1152; gi += 512) {
            int row = gi / 12, q = gi - row * 12;
            CP_ASYNC16(s2u(sQKV + row * STRQ + 192 + q * 8),
                       (const void*)(wqkv + (size_t)(192 + row) * 96 + q * 8));
        }
        CP_COMMIT();

        float acc[6][4] = {};
        #pragma unroll
        for (int ks = 0; ks < 6; ks++) {
            uint32_t bf[3][4];
            #pragma unroll
            for (int ng = 0; ng < 3; ng++)
                LDSM_X4(bf[ng][0], bf[ng][1], bf[ng][2], bf[ng][3],
                        bwA + ng * (16 * 104 * 2) + ks * 32);
            #pragma unroll
            for (int nt = 0; nt < 6; nt++) {
                int ng = nt >> 1, pr = (nt & 1) * 2;
                MMA_BF16(acc[nt], afr[ks][0], afr[ks][1], afr[ks][2], afr[ks][3],
                         bf[ng][pr], bf[ng][pr + 1]);
            }
        }
        #pragma unroll
        for (int nt = 0; nt < 6; nt++) {
            int lr = wm * 16 + (lane >> 2);
            int lc = wn * 48 + nt * 8 + (lane & 3) * 2;
            int gcol = 96 + lc;                       // k -> cols 96..191
            float bf0 = b_qkv[gcol], bf1 = b_qkv[gcol + 1];
            __nv_bfloat162 p0, p1;
            p0.x = __float2bfloat16(acc[nt][0] + bf0);
            p0.y = __float2bfloat16(acc[nt][1] + bf1);
            p1.x = __float2bfloat16(acc[nt][2] + bf0);
            p1.y = __float2bfloat16(acc[nt][3] + bf1);
            *(__nv_bfloat162*)(sQKV + lr * STRQ + gcol)       = p0;
            *(__nv_bfloat162*)(sQKV + (lr + 8) * STRQ + gcol) = p1;
        }
    }

    // -- chunk v (weights in v-slots) --
    {
        CP_WAIT0();
        __syncthreads();   // v weights visible; all warps done reading pWa (k)
        // prefetch q weights into pWa
        for (int gi = tid; gi < 1152; gi += 512) {
            int row = gi / 12, q = gi - row * 12;
            CP_ASYNC16(s2u(pWa + row * 104 + q * 8),
                       (const void*)(wqkv + (size_t)row * 96 + q * 8));
        }
        CP_COMMIT();

        float acc[6][4] = {};
        #pragma unroll
        for (int ks = 0; ks < 6; ks++) {
            uint32_t bf[3][4];
            #pragma unroll
            for (int ng = 0; ng < 3; ng++)
                LDSM_X4(bf[ng][0], bf[ng][1], bf[ng][2], bf[ng][3],
                        bwV + ng * (16 * STRQ * 2) + ks * 32);
            #pragma unroll
            for (int nt = 0; nt < 6; nt++) {
                int ng = nt >> 1, pr = (nt & 1) * 2;
                MMA_BF16(acc[nt], afr[ks][0], afr[ks][1], afr[ks][2], afr[ks][3],
                         bf[ng][pr], bf[ng][pr + 1]);
            }
        }
        __syncthreads();   // all warps done reading v-slot weights before overwrite
        #pragma unroll
        for (int nt = 0; nt < 6; nt++) {
            int lr = wm * 16 + (lane >> 2);
            int lc = wn * 48 + nt * 8 + (lane & 3) * 2;
            int gcol = 192 + lc;                      // v -> cols 192..287
            float bf0 = b_qkv[gcol], bf1 = b_qkv[gcol + 1];
            __nv_bfloat162 p0, p1;
            p0.x = __float2bfloat16(acc[nt][0] + bf0);
            p0.y = __float2bfloat16(acc[nt][1] + bf1);
            p1.x = __float2bfloat16(acc[nt][2] + bf0);
            p1.y = __float2bfloat16(acc[nt][3] + bf1);
            *(__nv_bfloat162*)(sQKV + lr * STRQ + gcol)       = p0;
            *(__nv_bfloat162*)(sQKV + (lr + 8) * STRQ + gcol) = p1;
        }
    }

    // -- chunk q (weights in pWa; output pre-scaled by QSCALE) --
    {
        CP_WAIT0();
        __syncthreads();   // q weights visible
        float acc[6][4] = {};
        #pragma unroll
        for (int ks = 0; ks < 6; ks++) {
            uint32_t bf[3][4];
            #pragma unroll
            for (int ng = 0; ng < 3; ng++)
                LDSM_X4(bf[ng][0], bf[ng][1], bf[ng][2], bf[ng][3],
                        bwA + ng * (16 * 104 * 2) + ks * 32);
            #pragma unroll
            for (int nt = 0; nt < 6; nt++) {
                int ng = nt >> 1, pr = (nt & 1) * 2;
                MMA_BF16(acc[nt], afr[ks][0], afr[ks][1], afr[ks][2], afr[ks][3],
                         bf[ng][pr], bf[ng][pr + 1]);
            }
        }
        __syncthreads();   // everyone done with LN1/q-slots (A-frags cached anyway)
        #pragma unroll
        for (int nt = 0; nt < 6; nt++) {
            int lr = wm * 16 + (lane >> 2);
            int lc = wn * 48 + nt * 8 + (lane & 3) * 2;
            float bf0 = b_qkv[lc], bf1 = b_qkv[lc + 1];
            __nv_bfloat162 p0, p1;
            p0.x = __float2bfloat16((acc[nt][0] + bf0) * QSCALE);
            p0.y = __float2bfloat16((acc[nt][1] + bf1) * QSCALE);
            p1.x = __float2bfloat16((acc[nt][2] + bf0) * QSCALE);
            p1.y = __float2bfloat16((acc[nt][3] + bf1) * QSCALE);
            *(__nv_bfloat162*)(sQKV + lr * STRQ + lc)       = p0;
            *(__nv_bfloat162*)(sQKV + (lr + 8) * STRQ + lc) = p1;
        }
    }
    __syncthreads();

    // ---- phase 2: attention + Wproj prefetch into pWa ----
    for (int gi = tid; gi < 1152; gi += 512) {
        int row = gi / 12, q = gi - row * 12;
        CP_ASYNC16(s2u(pWa + row * 104 + q * 8),
                   (const void*)(wproj + (size_t)row * 96 + q * 8));
    }
    CP_COMMIT();
    {
        const uint32_t ONEB = 0x3F803F80u;   // bf16x2 {1.0, 1.0}
        const int wbit = ((lane >> 1) & 1) << 2;   // column w-label bit (per lane)
        for (int u = warp; u < 48; u += 16) {
            int head = u >> 3, rtile = u & 7;
            int hoff = head * 16, r0 = rtile * 16;
            uint32_t qa[4];
            LDSM_X4(qa[0], qa[1], qa[2], qa[3],
                    s2u(sQKV + (r0 + (lane & 15)) * STRQ + hoff + (lane >> 4) * 8));
            const int rb0 = bits3(r0 + (lane >> 2));
            const int rb1 = bits3(r0 + 8 + (lane >> 2));
            const uint32_t kaddr = s2u(sQKV + (((lane >> 4) << 3) + (lane & 7)) * STRQ
                                            + 96 + hoff + ((lane >> 3) & 1) * 8);
            const uint32_t vaddr = s2u(sQKV + (lane & 15) * STRQ + 192 + hoff + (lane >> 4) * 8);
            float o0[4] = {}, o1[4] = {}, osum[4] = {};
            #pragma unroll
            for (int jg = 0; jg < 8; jg++) {
                uint32_t kb[4];
                LDSM_X4(kb[0], kb[1], kb[2], kb[3], kaddr + jg * (16 * STRQ * 2));
                float c0[4] = {}, c1[4] = {};
                MMA_BF16(c0, qa[0], qa[1], qa[2], qa[3], kb[0], kb[1]);
                MMA_BF16(c1, qa[0], qa[1], qa[2], qa[3], kb[2], kb[3]);
                __nv_bfloat162 a0 = __floats2bfloat162_rn(ex2f(c0[0]), ex2f(c0[1]));
                __nv_bfloat162 a1 = __floats2bfloat162_rn(ex2f(c0[2]), ex2f(c0[3]));
                __nv_bfloat162 a2 = __floats2bfloat162_rn(ex2f(c1[0]), ex2f(c1[1]));
                __nv_bfloat162 a3 = __floats2bfloat162_rn(ex2f(c1[2]), ex2f(c1[3]));
                uint32_t u0 = *(uint32_t*)&a0, u1 = *(uint32_t*)&a1;
                uint32_t u2 = *(uint32_t*)&a2, u3 = *(uint32_t*)&a3;
                if (amask) {
                    int clab = ((jg >> 2) & 1) | (((jg >> 1) & 1) << 1) | wbit;
                    bool k0 = (((clab ^ rb0) & amask) == 0);
                    bool k1 = (((clab ^ rb1) & amask) == 0);
                    u0 = k0 ? u0 : 0u;  u2 = k0 ? u2 : 0u;
                    u1 = k1 ? u1 : 0u;  u3 = k1 ? u3 : 0u;
                }
                uint32_t vb[4];
                LDSM_X4_T(vb[0], vb[1], vb[2], vb[3], vaddr + jg * (16 * STRQ * 2));
                MMA_BF16(o0, u0, u1, u2, u3, vb[0], vb[1]);
                MMA_BF16(o1, u0, u1, u2, u3, vb[2], vb[3]);
                MMA_BF16(osum, u0, u1, u2, u3, ONEB, ONEB);
            }
            float inv0 = 1.0f / osum[0];
            float inv1 = 1.0f / osum[2];
            int r = r0 + (lane >> 2);
            #pragma unroll
            for (int nt = 0; nt < 2; nt++) {
                int col = hoff + nt * 8 + (lane & 3) * 2;
                float* o = nt ? o1 : o0;
                __nv_bfloat162 w0 = __floats2bfloat162_rn(o[0] * inv0, o[1] * inv0);
                __nv_bfloat162 w1 = __floats2bfloat162_rn(o[2] * inv1, o[3] * inv1);
                *(__nv_bfloat162*)(sQKV + r * STRQ + col)       = w0;
                *(__nv_bfloat162*)(sQKV + (r + 8) * STRQ + col) = w1;
            }
        }
    }
    CP_WAIT0();
    __syncthreads();

    // ---- phase 3: proj GEMM (A = attn-out q-slots, B = Wproj in pWa) -> yf ----
    {
        float acc[6][4] = {};
        #pragma unroll
        for (int ks = 0; ks < 6; ks++) {
            uint32_t a[4], bf[3][4];
            LDSM_X4(a[0], a[1], a[2], a[3], aq + ks * 32);
            #pragma unroll
            for (int ng = 0; ng < 3; ng++)
                LDSM_X4(bf[ng][0], bf[ng][1], bf[ng][2], bf[ng][3],
                        bwA + ng * (16 * 104 * 2) + ks * 32);
            #pragma unroll
            for (int nt = 0; nt < 6; nt++) {
                int ng = nt >> 1, pr = (nt & 1) * 2;
                MMA_BF16(acc[nt], a[0], a[1], a[2], a[3], bf[ng][pr], bf[ng][pr + 1]);
            }
        }
        #pragma unroll
        for (int nt = 0; nt < 6; nt++) {
            int lr = wm * 16 + (lane >> 2);
            int lc = wn * 48 + nt * 8 + (lane & 3) * 2;
            float bf0 = b_proj[lc], bf1 = b_proj[lc + 1];
            yf[lr * 148 + 48 + lc]           = acc[nt][0] + bf0;
            yf[lr * 148 + 48 + lc + 1]       = acc[nt][1] + bf1;
            yf[(lr + 8) * 148 + 48 + lc]     = acc[nt][2] + bf0;
            yf[(lr + 8) * 148 + 48 + lc + 1] = acc[nt][3] + bf1;
        }
    }
    __syncthreads();

    // ---- phase 4: y = proj + x -> GMEM scratch; LN2 -> pLN2 ----
    for (int tok = warp; tok < 128; tok += 16) {
        int dt = tok >> 6, dh = (tok >> 3) & 7, dw = tok & 7;
        int t = tb * 2 + dt, h = hb * 8 + dh, w = wb * 8 + dw;
        int ti = (t + 1) & 7, hi = (h + 4) & 127, wi = (w + 4) & 127;
        size_t m = ((size_t)((bi * 8 + ti) * 128 + hi)) * 128 + wi;
        const float* xrow = x + m * 96;
        const float* yrow = yf + tok * 148 + 48;
        float v0 = yrow[lane]      + xrow[lane];
        float v1 = yrow[lane + 32] + xrow[lane + 32];
        float v2 = yrow[lane + 64] + xrow[lane + 64];
        float* gy = yscr + m * 96;
        gy[lane]      = v0;
        gy[lane + 32] = v1;
        gy[lane + 64] = v2;
        float s  = v0 + v1 + v2;
        float s2 = v0 * v0 + v1 * v1 + v2 * v2;
        #pragma unroll
        for (int o = 16; o; o >>= 1) {
            s  += __shfl_xor_sync(0xffffffffu, s,  o);
            s2 += __shfl_xor_sync(0xffffffffu, s2, o);
        }
        float mean = s * (1.0f / 96.0f);
        float var  = s2 * (1.0f / 96.0f) - mean * mean;
        float rstd = rsqrtf(var + 1e-5f);
        __nv_bfloat16* orow = pLN2 + tok * 104;
        orow[lane]      = __float2bfloat16((v0 - mean) * rstd * g2[lane]      + b2[lane]);
        orow[lane + 32] = __float2bfloat16((v1 - mean) * rstd * g2[lane + 32] + b2[lane + 32]);
        orow[lane + 64] = __float2bfloat16((v2 - mean) * rstd * g2[lane + 64] + b2[lane + 64]);
    }
    __syncthreads();   // yf consumed -> kv region free for MLP weight buffers

    // ---- phase 5: MLP, 4 chunks of 96, double-buffered weights (cp.async) ----
    // bufW1: 96 rows x 96 at cols 96..191; bufW2: 96 rows x 96 at cols 192..287
    float acc2[6][4] = {};
    const uint32_t aln = s2u(pLN2 + (wm * 16 + (lane & 15)) * 104 + (lane >> 4) * 8);
    const uint32_t ah2 = s2u(sQKV + (wm * 16 + (lane & 15)) * STRQ + (lane >> 4) * 8);
    const uint32_t bw1 = s2u(sQKV + 96 + (wn * 48 + ((lane >> 4) << 3) + (lane & 7)) * STRQ
                                  + ((lane >> 3) & 1) * 8);
    const uint32_t bw2 = s2u(sQKV + 192 + (wn * 48 + ((lane >> 4) << 3) + (lane & 7)) * STRQ
                                  + ((lane >> 3) & 1) * 8);

    // prefetch W1 chunk 0 (96 rows x 96 cols)
    for (int gi = tid; gi < 1152; gi += 512) {
        int row = gi / 12, q = gi - (gi / 12) * 12;
        CP_ASYNC16(s2u(sQKV + row * STRQ + 96 + q * 8),
                   (const void*)(w1 + (size_t)row * 96 + q * 8));
    }
    CP_COMMIT();

    for (int c = 0; c < 4; c++) {
        CP_WAIT0();
        __syncthreads();   // W1c ready; hidden free (prev fc2 done)
        // prefetch W2 chunk c -> bufW2 (96 rows x 96 K-cols)
        for (int gi = tid; gi < 1152; gi += 512) {
            int row = gi / 12, q = gi - (gi / 12) * 12;
            CP_ASYNC16(s2u(sQKV + row * STRQ + 192 + q * 8),
                       (const void*)(w2 + (size_t)row * 384 + c * 96 + q * 8));
        }
        CP_COMMIT();
        // fc1 chunk: (128x96)@(96x96)^T + bias + GELU -> hidden (q-slots cols 0..95)
        {
            float a1[6][4] = {};
            #pragma unroll
            for (int ks = 0; ks < 6; ks++) {
                uint32_t a[4], bf[3][4];
                LDSM_X4(a[0], a[1], a[2], a[3], aln + ks * 32);
                #pragma unroll
                for (int ng = 0; ng < 3; ng++)
                    LDSM_X4(bf[ng][0], bf[ng][1], bf[ng][2], bf[ng][3],
                            bw1 + ng * (16 * STRQ * 2) + ks * 32);
                #pragma unroll
                for (int nt = 0; nt < 6; nt++) {
                    int ng = nt >> 1, pr = (nt & 1) * 2;
                    MMA_BF16(a1[nt], a[0], a[1], a[2], a[3], bf[ng][pr], bf[ng][pr + 1]);
                }
            }
            #pragma unroll
            for (int nt = 0; nt < 6; nt++) {
                int lr = wm * 16 + (lane >> 2);
                int lc = wn * 48 + nt * 8 + (lane & 3) * 2;
                int gcol = c * 96 + lc;
                float bf0 = bias1[gcol], bf1 = bias1[gcol + 1];
                float v0 = gelu_t(a1[nt][0] + bf0);
                float v1 = gelu_t(a1[nt][1] + bf1);
                float v2 = gelu_t(a1[nt][2] + bf0);
                float v3 = gelu_t(a1[nt][3] + bf1);
                __nv_bfloat162 p0, p1;
                p0.x = __float2bfloat16(v0); p0.y = __float2bfloat16(v1);
                p1.x = __float2bfloat16(v2); p1.y = __float2bfloat16(v3);
                *(__nv_bfloat162*)(sQKV + lr * STRQ + lc)       = p0;
                *(__nv_bfloat162*)(sQKV + (lr + 8) * STRQ + lc) = p1;
            }
        }
        CP_WAIT0();
        __syncthreads();   // W2c ready; hidden ready; bufW1 free
        // prefetch W1 chunk c+1 -> bufW1 (overlaps fc2)
        if (c < 3) {
            for (int gi = tid; gi < 1152; gi += 512) {
                int row = gi / 12, q = gi - (gi / 12) * 12;
                CP_ASYNC16(s2u(sQKV + row * STRQ + 96 + q * 8),
                           (const void*)(w1 + (size_t)((c + 1) * 96 + row) * 96 + q * 8));
            }
        }
        CP_COMMIT();
        // fc2 partial: (128x96)@(96x96)^T accumulate
        #pragma unroll
        for (int ks = 0; ks < 6; ks++) {
            uint32_t a[4], bf[3][4];
            LDSM_X4(a[0], a[1], a[2], a[3], ah2 + ks * 32);
            #pragma unroll
            for (int ng = 0; ng < 3; ng++)
                LDSM_X4(bf[ng][0], bf[ng][1], bf[ng][2], bf[ng][3],
                        bw2 + ng * (16 * STRQ * 2) + ks * 32);
            #pragma unroll
            for (int nt = 0; nt < 6; nt++) {
                int ng = nt >> 1, pr = (nt & 1) * 2;
                MMA_BF16(acc2[nt], a[0], a[1], a[2], a[3], bf[ng][pr], bf[ng][pr + 1]);
            }
        }
    }

    // ---- phase 6: out = fc2 + bias2 + y(gmem), scatter natural order (fp32) ----
    #pragma unroll
    for (int hh = 0; hh < 2; hh++) {
        int lr = wm * 16 + (lane >> 2) + hh * 8;
        int dt = lr >> 6, dh = (lr >> 3) & 7, dw = lr & 7;
        int t = tb * 2 + dt, h = hb * 8 + dh, w = wb * 8 + dw;
        int ti = (t + 1) & 7, hi = (h + 4) & 127, wi = (w + 4) & 127;
        size_t m = ((size_t)((bi * 8 + ti) * 128 + hi)) * 128 + wi;
        #pragma unroll
        for (int nt = 0; nt < 6; nt++) {
            int lc = wn * 48 + nt * 8 + (lane & 3) * 2;
            float2 yv = *(const float2*)(yscr + m * 96 + lc);
            float v0 = acc2[nt][hh * 2 + 0] + bias2[lc]     + yv.x;
            float v1 = acc2[nt][hh * 2 + 1] + bias2[lc + 1] + yv.y;
            *(float2*)(out + m * 96 + lc) = make_float2(v0, v1);
        }
    }
}

// ---------------- launch ----------------
extern "C" void kernel_launch(void* const* d_in, const int* in_sizes, int n_in,
                              void* d_out, int out_size)
{
    const float* x      = (const float*)d_in[0];
    const float* g1     = (const float*)d_in[2];
    const float* b1     = (const float*)d_in[3];
    const float* w_qkv  = (const float*)d_in[4];
    const float* b_qkv  = (const float*)d_in[5];
    const float* w_proj = (const float*)d_in[6];
    const float* b_proj = (const float*)d_in[7];
    const float* g2     = (const float*)d_in[8];
    const float* b2     = (const float*)d_in[9];
    const float* w_fc1  = (const float*)d_in[10];
    const float* b_fc1  = (const float*)d_in[11];
    const float* w_fc2  = (const float*)d_in[12];
    const float* b_fc2  = (const float*)d_in[13];
    float* out = (float*)d_out;

    __nv_bfloat16 *p_wb;
    float *p_y;
    cudaGetSymbolAddress((void**)&p_wb, g_wb);
    cudaGetSymbolAddress((void**)&p_y,  g_y);

    static bool attr_set = false;
    if (!attr_set) {
        cudaFuncSetAttribute(mono_kernel,
                             cudaFuncAttributeMaxDynamicSharedMemorySize, SMEM_MONO);
        attr_set = true;
    }

    convert_w<<<(110592 + 255) / 256, 256>>>(w_qkv, w_proj, w_fc1, w_fc2, p_wb);

    mono_kernel<<<NWIN, 512, SMEM_MONO>>>(
        x, g1, b1,
        p_wb + WB_QKV, b_qkv, p_wb + WB_PROJ, b_proj,
        g2, b2,
        p_wb + WB_FC1, b_fc1, p_wb + WB_FC2, b_fc2,
        p_y, out);
}